// round 14
// baseline (speedup 1.0000x reference)
#include <cuda_runtime.h>
#include <cuda_fp16.h>
#include <cstdint>
#include <cstddef>

// ---------------------------------------------------------------------------
// Problem dims (fixed)
// ---------------------------------------------------------------------------
#define LAYERS 6
#define BATCH  4
#define SEQ    512
#define DMODEL 1024
#define NHEAD  16
#define DHEAD  64
#define DFF    4096
#define ROWS   (BATCH * SEQ)           // 2048
#define BH     (BATCH * NHEAD)         // 64
#define QKVN   (3 * DMODEL)            // 3072

// ---------------------------------------------------------------------------
// Scratch (device globals; no allocation allowed)
// ---------------------------------------------------------------------------
__device__ float g_x  [ROWS * DMODEL];
__device__ float g_tmp[ROWS * DMODEL];
__device__ float g_sc [(size_t)BH * SEQ * SEQ];

__device__ __half g_xh  [ROWS * DMODEL];
__device__ __half g_xl  [ROWS * DMODEL];
__device__ __half g_qkvh[(size_t)ROWS * QKVN];
__device__ __half g_qkvl[(size_t)ROWS * QKVN];
__device__ __half g_c16 [ROWS * DMODEL];
__device__ __half g_f16 [(size_t)ROWS * DFF];
__device__ __half g_p16 [(size_t)BH * SEQ * SEQ];

#define MEG (1024 * 1024)
#define W_TOTAL ((size_t)96 * MEG)
__device__ __half g_wh[W_TOTAL];
__device__ __half g_wl[W_TOTAL];

#define OFF_QKV1 ((size_t)0 * MEG)
#define OFF_O1   ((size_t)18 * MEG)
#define OFF_QKV2 ((size_t)24 * MEG)
#define OFF_O2   ((size_t)42 * MEG)
#define OFF_F1   ((size_t)48 * MEG)
#define OFF_F2   ((size_t)72 * MEG)

// ---------------------------------------------------------------------------
// PTX helpers
// ---------------------------------------------------------------------------
__device__ __forceinline__ uint32_t smem_u32(const void* p) {
    uint32_t a;
    asm("{ .reg .u64 t; cvta.to.shared.u64 t, %1; cvt.u32.u64 %0, t; }"
        : "=r"(a) : "l"(p));
    return a;
}
__device__ __forceinline__ void cp16(uint32_t dst, const void* src) {
    asm volatile("cp.async.cg.shared.global [%0], [%1], 16;"
                 :: "r"(dst), "l"(src) : "memory");
}
#define CP_COMMIT() asm volatile("cp.async.commit_group;" ::: "memory")
#define CP_WAIT(n)  asm volatile("cp.async.wait_group %0;" :: "n"(n) : "memory")

__device__ __forceinline__ void ldsm_x4(uint32_t a[4], uint32_t addr) {
    asm volatile("ldmatrix.sync.aligned.m8n8.x4.shared.b16 {%0,%1,%2,%3}, [%4];"
                 : "=r"(a[0]), "=r"(a[1]), "=r"(a[2]), "=r"(a[3]) : "r"(addr));
}
__device__ __forceinline__ void ldsm_x2(uint32_t a[2], uint32_t addr) {
    asm volatile("ldmatrix.sync.aligned.m8n8.x2.shared.b16 {%0,%1}, [%2];"
                 : "=r"(a[0]), "=r"(a[1]) : "r"(addr));
}
__device__ __forceinline__ void ldsm_x2t(uint32_t a[2], uint32_t addr) {
    asm volatile("ldmatrix.sync.aligned.m8n8.x2.trans.shared.b16 {%0,%1}, [%2];"
                 : "=r"(a[0]), "=r"(a[1]) : "r"(addr));
}
// f32-accumulator fp16 MMA (hi terms)
__device__ __forceinline__ void mma_f16(float c[4], const uint32_t a[4],
                                        const uint32_t b[2]) {
    asm volatile("mma.sync.aligned.m16n8k16.row.col.f32.f16.f16.f32 "
                 "{%0,%1,%2,%3}, {%4,%5,%6,%7}, {%8,%9}, {%0,%1,%2,%3};"
                 : "+f"(c[0]), "+f"(c[1]), "+f"(c[2]), "+f"(c[3])
                 : "r"(a[0]), "r"(a[1]), "r"(a[2]), "r"(a[3]),
                   "r"(b[0]), "r"(b[1]));
}
// f16-accumulator fp16 MMA (lo-correction terms; values ~5e-4 of result)
__device__ __forceinline__ void mma_f16h(uint32_t c[2], const uint32_t a[4],
                                         const uint32_t b[2]) {
    asm volatile("mma.sync.aligned.m16n8k16.row.col.f16.f16.f16.f16 "
                 "{%0,%1}, {%2,%3,%4,%5}, {%6,%7}, {%0,%1};"
                 : "+r"(c[0]), "+r"(c[1])
                 : "r"(a[0]), "r"(a[1]), "r"(a[2]), "r"(a[3]),
                   "r"(b[0]), "r"(b[1]));
}
// combine fp16 lo-accumulator into fp32 accumulator
__device__ __forceinline__ void comb(float c[4], const uint32_t l[2]) {
    float2 fa = __half22float2(*(const __half2*)&l[0]);
    float2 fb = __half22float2(*(const __half2*)&l[1]);
    c[0] += fa.x; c[1] += fa.y; c[2] += fb.x; c[3] += fb.y;
}
__device__ __forceinline__ void store_h2(__half* H, size_t off, float a, float b) {
    __half2 hv;
    hv.x = __float2half_rn(a); hv.y = __float2half_rn(b);
    *(__half2*)(H + off) = hv;
}
__device__ __forceinline__ void store_split2(__half* H, __half* L,
                                             size_t off, float a, float b) {
    __half ha = __float2half_rn(a), hb = __float2half_rn(b);
    __half la = __float2half_rn(a - __half2float(ha));
    __half lb = __float2half_rn(b - __half2float(hb));
    __half2 hv; hv.x = ha; hv.y = hb;
    __half2 lv; lv.x = la; lv.y = lb;
    *(__half2*)(H + off) = hv;
    *(__half2*)(L + off) = lv;
}

// ---------------------------------------------------------------------------
// Common tile constants
// ---------------------------------------------------------------------------
#define BKC      32
#define APITCH   80
#define TILE_B   (128 * APITCH)        // 10240

// ---------------------------------------------------------------------------
// 3-term GEMM (QKV): hi in f32-accum, cross terms in f16-accum. 2-stage.
// ---------------------------------------------------------------------------
#define STG3_B   (4 * TILE_B)          // 40960
#define GEMM3_SMEM (2 * STG3_B)        // 81920

__global__ void __launch_bounds__(256, 2)
mm_gemm3(const __half* __restrict__ Ah, const __half* __restrict__ Al,
         const __half* __restrict__ Bh, const __half* __restrict__ Bl,
         __half* __restrict__ Ch, __half* __restrict__ Cl,
         int M, int N, int K)
{
    extern __shared__ char smem[];
    const uint32_t sb = smem_u32(smem);
    const int tid = threadIdx.x;
    const int wid = tid >> 5, lane = tid & 31;
    const int wm = wid >> 2, wn = wid & 3;
    const int m0 = blockIdx.y * 128, n0 = blockIdx.x * 128;

    const int r0 = tid >> 1;
    const int c0 = (tid & 1) * 2;

    float acc[4][4][4];
    uint32_t accL[4][4][2];
    #pragma unroll
    for (int i = 0; i < 4; ++i)
        #pragma unroll
        for (int j = 0; j < 4; ++j) {
            #pragma unroll
            for (int t = 0; t < 4; ++t) acc[i][j][t] = 0.f;
            accL[i][j][0] = 0u; accL[i][j][1] = 0u;
        }

    const int NCHUNK = K / BKC;

    auto load_stage = [&](int stage, int chunk) {
        const uint32_t st = sb + stage * STG3_B;
        const int k0 = chunk * BKC;
        #pragma unroll
        for (int u = 0; u < 2; ++u) {
            const int c = c0 + u;
            const uint32_t so = (uint32_t)(r0 * APITCH + c * 16);
            const size_t ga = (size_t)(m0 + r0) * K + k0 + c * 8;
            const size_t gb = (size_t)(n0 + r0) * K + k0 + c * 8;
            cp16(st + 0 * TILE_B + so, Ah + ga);
            cp16(st + 1 * TILE_B + so, Al + ga);
            cp16(st + 2 * TILE_B + so, Bh + gb);
            cp16(st + 3 * TILE_B + so, Bl + gb);
        }
    };

    load_stage(0, 0);
    CP_COMMIT();

    for (int ch = 0; ch < NCHUNK; ++ch) {
        CP_WAIT(0);
        __syncthreads();
        if (ch + 1 < NCHUNK) load_stage((ch + 1) & 1, ch + 1);
        CP_COMMIT();

        const uint32_t st  = sb + (ch & 1) * STG3_B;
        const uint32_t bAh = st, bBh = st + 2 * TILE_B;

        #pragma unroll
        for (int ks = 0; ks < 2; ++ks) {
            const int kb = ks * 32;
            uint32_t fbh[4][2], fbl[4][2];
            #pragma unroll
            for (int nt = 0; nt < 4; ++nt) {
                uint32_t addr = bBh
                    + (uint32_t)((wn * 32 + nt * 8 + (lane & 7)) * APITCH
                                 + kb + ((lane >> 3) & 1) * 16);
                ldsm_x2(fbh[nt], addr);
                ldsm_x2(fbl[nt], addr + TILE_B);
            }
            #pragma unroll
            for (int mt = 0; mt < 4; ++mt) {
                uint32_t addr = bAh
                    + (uint32_t)((wm * 64 + mt * 16 + (lane & 15)) * APITCH
                                 + kb + (lane >> 4) * 16);
                uint32_t fah[4], fal[4];
                ldsm_x4(fah, addr);
                ldsm_x4(fal, addr + TILE_B);
                #pragma unroll
                for (int nt = 0; nt < 4; ++nt) {
                    mma_f16(acc[mt][nt], fah, fbh[nt]);
                    mma_f16h(accL[mt][nt], fah, fbl[nt]);
                    mma_f16h(accL[mt][nt], fal, fbh[nt]);
                }
            }
        }
        __syncthreads();
    }

    const int rbase = m0 + wm * 64 + (lane >> 2);
    const int cbase = n0 + wn * 32 + (lane & 3) * 2;
    #pragma unroll
    for (int mt = 0; mt < 4; ++mt) {
        #pragma unroll
        for (int nt = 0; nt < 4; ++nt) {
            float* c = acc[mt][nt];
            comb(c, accL[mt][nt]);
            const int rr = rbase + mt * 16;
            const int cc = cbase + nt * 8;
            store_split2(Ch, Cl, (size_t)rr * N + cc,       c[0], c[1]);
            store_split2(Ch, Cl, (size_t)(rr + 8) * N + cc, c[2], c[3]);
        }
    }
}

// ---------------------------------------------------------------------------
// 2-term GEMM (O/F1/F2): hi f32-accum, lo f16-accum. 3-stage pipeline.
// ---------------------------------------------------------------------------
#define STG2_B   (3 * TILE_B)          // 30720
#define G2_NST   3
#define GEMM2_SMEM (G2_NST * STG2_B)   // 92160

__global__ void __launch_bounds__(256, 2)
mm_gemm2(const __half* __restrict__ A,
         const __half* __restrict__ Bh, const __half* __restrict__ Bl,
         float* __restrict__ Cf, __half* __restrict__ C16,
         int M, int N, int K, int relu)
{
    extern __shared__ char smem[];
    const uint32_t sb = smem_u32(smem);
    const int tid = threadIdx.x;
    const int wid = tid >> 5, lane = tid & 31;
    const int wm = wid >> 2, wn = wid & 3;
    const int m0 = blockIdx.y * 128, n0 = blockIdx.x * 128;

    const int r0 = tid >> 1;
    const int c0 = (tid & 1) * 2;

    float acc[4][4][4];
    uint32_t accL[4][4][2];
    #pragma unroll
    for (int i = 0; i < 4; ++i)
        #pragma unroll
        for (int j = 0; j < 4; ++j) {
            #pragma unroll
            for (int t = 0; t < 4; ++t) acc[i][j][t] = 0.f;
            accL[i][j][0] = 0u; accL[i][j][1] = 0u;
        }

    const int NCHUNK = K / BKC;

    auto load_stage = [&](int stage, int chunk) {
        const uint32_t st = sb + stage * STG2_B;
        const int k0 = chunk * BKC;
        #pragma unroll
        for (int u = 0; u < 2; ++u) {
            const int c = c0 + u;
            const uint32_t so = (uint32_t)(r0 * APITCH + c * 16);
            const size_t ga = (size_t)(m0 + r0) * K + k0 + c * 8;
            const size_t gb = (size_t)(n0 + r0) * K + k0 + c * 8;
            cp16(st + 0 * TILE_B + so, A + ga);
            cp16(st + 1 * TILE_B + so, Bh + gb);
            cp16(st + 2 * TILE_B + so, Bl + gb);
        }
    };

    load_stage(0, 0); CP_COMMIT();
    if (NCHUNK > 1) load_stage(1, 1);
    CP_COMMIT();

    for (int ch = 0; ch < NCHUNK; ++ch) {
        CP_WAIT(1);
        __syncthreads();
        if (ch + 2 < NCHUNK) load_stage((ch + 2) % G2_NST, ch + 2);
        CP_COMMIT();

        const uint32_t st  = sb + (ch % G2_NST) * STG2_B;
        const uint32_t bA  = st, bBh = st + TILE_B;

        #pragma unroll
        for (int ks = 0; ks < 2; ++ks) {
            const int kb = ks * 32;
            uint32_t fbh[4][2], fbl[4][2];
            #pragma unroll
            for (int nt = 0; nt < 4; ++nt) {
                uint32_t addr = bBh
                    + (uint32_t)((wn * 32 + nt * 8 + (lane & 7)) * APITCH
                                 + kb + ((lane >> 3) & 1) * 16);
                ldsm_x2(fbh[nt], addr);
                ldsm_x2(fbl[nt], addr + TILE_B);
            }
            #pragma unroll
            for (int mt = 0; mt < 4; ++mt) {
                uint32_t addr = bA
                    + (uint32_t)((wm * 64 + mt * 16 + (lane & 15)) * APITCH
                                 + kb + (lane >> 4) * 16);
                uint32_t fa[4];
                ldsm_x4(fa, addr);
                #pragma unroll
                for (int nt = 0; nt < 4; ++nt) {
                    mma_f16(acc[mt][nt], fa, fbh[nt]);
                    mma_f16h(accL[mt][nt], fa, fbl[nt]);
                }
            }
        }
    }

    const int rbase = m0 + wm * 64 + (lane >> 2);
    const int cbase = n0 + wn * 32 + (lane & 3) * 2;
    #pragma unroll
    for (int mt = 0; mt < 4; ++mt) {
        #pragma unroll
        for (int nt = 0; nt < 4; ++nt) {
            float* c = acc[mt][nt];
            comb(c, accL[mt][nt]);
            if (relu) {
                c[0] = fmaxf(c[0], 0.f); c[1] = fmaxf(c[1], 0.f);
                c[2] = fmaxf(c[2], 0.f); c[3] = fmaxf(c[3], 0.f);
            }
            const int rr = rbase + mt * 16;
            const int cc = cbase + nt * 8;
            if (Cf) {
                *(float2*)(Cf + (size_t)rr * N + cc)       = make_float2(c[0], c[1]);
                *(float2*)(Cf + (size_t)(rr + 8) * N + cc) = make_float2(c[2], c[3]);
            }
            if (C16) {
                store_h2(C16, (size_t)rr * N + cc,       c[0], c[1]);
                store_h2(C16, (size_t)(rr + 8) * N + cc, c[2], c[3]);
            }
        }
    }
}

// ---------------------------------------------------------------------------
// Attention scores (3-term): hi f32-accum, cross f16-accum.
// ---------------------------------------------------------------------------
#define SPITCH 144
#define STILE  (128 * SPITCH)          // 18432
#define SC_SMEM (4 * STILE)            // 73728

__global__ void __launch_bounds__(256, 2)
attn_score_kernel(const __half* __restrict__ QKVh,
                  const __half* __restrict__ QKVl,
                  float* __restrict__ sc, int masked)
{
    const int bh = blockIdx.z, b = bh >> 4, h = bh & 15;
    const int q0 = blockIdx.y * 128, k0 = blockIdx.x * 128;
    if (masked && k0 >= q0 + 128) return;

    extern __shared__ char smem[];
    const uint32_t sb = smem_u32(smem);
    const int tid = threadIdx.x;
    const int wid = tid >> 5, lane = tid & 31;
    const int wm = wid >> 2, wn = wid & 3;

    {
        const int r  = tid >> 1;
        const int cb = (tid & 1) * 4;
        #pragma unroll
        for (int u = 0; u < 4; ++u) {
            const int c = cb + u;
            const uint32_t so = (uint32_t)(r * SPITCH + c * 16);
            const size_t gq = (size_t)(b * SEQ + q0 + r) * QKVN + h * DHEAD + c * 8;
            const size_t gk = (size_t)(b * SEQ + k0 + r) * QKVN + DMODEL + h * DHEAD + c * 8;
            cp16(sb + 0 * STILE + so, QKVh + gq);
            cp16(sb + 1 * STILE + so, QKVl + gq);
            cp16(sb + 2 * STILE + so, QKVh + gk);
            cp16(sb + 3 * STILE + so, QKVl + gk);
        }
    }
    CP_COMMIT();
    CP_WAIT(0);
    __syncthreads();

    float acc[4][4][4];
    uint32_t accL[4][4][2];
    #pragma unroll
    for (int i = 0; i < 4; ++i)
        #pragma unroll
        for (int j = 0; j < 4; ++j) {
            #pragma unroll
            for (int t = 0; t < 4; ++t) acc[i][j][t] = 0.f;
            accL[i][j][0] = 0u; accL[i][j][1] = 0u;
        }

    #pragma unroll
    for (int ks = 0; ks < 4; ++ks) {
        const int kb = ks * 32;
        uint32_t fbh[4][2], fbl[4][2];
        #pragma unroll
        for (int nt = 0; nt < 4; ++nt) {
            uint32_t addr = sb + 2 * STILE
                + (uint32_t)((wn * 32 + nt * 8 + (lane & 7)) * SPITCH
                             + kb + ((lane >> 3) & 1) * 16);
            ldsm_x2(fbh[nt], addr);
            ldsm_x2(fbl[nt], addr + STILE);
        }
        #pragma unroll
        for (int mt = 0; mt < 4; ++mt) {
            uint32_t addr = sb
                + (uint32_t)((wm * 64 + mt * 16 + (lane & 15)) * SPITCH
                             + kb + (lane >> 4) * 16);
            uint32_t fah[4], fal[4];
            ldsm_x4(fah, addr);
            ldsm_x4(fal, addr + STILE);
            #pragma unroll
            for (int nt = 0; nt < 4; ++nt) {
                mma_f16(acc[mt][nt], fah, fbh[nt]);
                mma_f16h(accL[mt][nt], fah, fbl[nt]);
                mma_f16h(accL[mt][nt], fal, fbh[nt]);
            }
        }
    }

    float* S = sc + (size_t)bh * SEQ * SEQ;
    const int rbase = q0 + wm * 64 + (lane >> 2);
    const int cbase = k0 + wn * 32 + (lane & 3) * 2;
    #pragma unroll
    for (int mt = 0; mt < 4; ++mt) {
        #pragma unroll
        for (int nt = 0; nt < 4; ++nt) {
            float* c = acc[mt][nt];
            comb(c, accL[mt][nt]);
            const int rr = rbase + mt * 16;
            const int cc = cbase + nt * 8;
            *(float2*)(S + (size_t)rr * SEQ + cc) =
                make_float2(c[0] * 0.125f, c[1] * 0.125f);
            *(float2*)(S + (size_t)(rr + 8) * SEQ + cc) =
                make_float2(c[2] * 0.125f, c[3] * 0.125f);
        }
    }
}

// ---------------------------------------------------------------------------
// Block reductions
// ---------------------------------------------------------------------------
__device__ __forceinline__ float block_reduce_sum(float v, float* shm) {
    __syncthreads();
    int lane = threadIdx.x & 31, w = threadIdx.x >> 5;
    #pragma unroll
    for (int o = 16; o; o >>= 1) v += __shfl_xor_sync(0xffffffff, v, o);
    if (lane == 0) shm[w] = v;
    __syncthreads();
    int nw = blockDim.x >> 5;
    float r = (threadIdx.x < nw) ? shm[threadIdx.x] : 0.f;
    if (w == 0) {
        #pragma unroll
        for (int o = 16; o; o >>= 1) r += __shfl_xor_sync(0xffffffff, r, o);
        if (lane == 0) shm[0] = r;
    }
    __syncthreads();
    return shm[0];
}
__device__ __forceinline__ float block_reduce_max(float v, float* shm) {
    __syncthreads();
    int lane = threadIdx.x & 31, w = threadIdx.x >> 5;
    #pragma unroll
    for (int o = 16; o; o >>= 1) v = fmaxf(v, __shfl_xor_sync(0xffffffff, v, o));
    if (lane == 0) shm[w] = v;
    __syncthreads();
    int nw = blockDim.x >> 5;
    float r = (threadIdx.x < nw) ? shm[threadIdx.x] : -3.4e38f;
    if (w == 0) {
        #pragma unroll
        for (int o = 16; o; o >>= 1) r = fmaxf(r, __shfl_xor_sync(0xffffffff, r, o));
        if (lane == 0) shm[0] = r;
    }
    __syncthreads();
    return shm[0];
}

// ---------------------------------------------------------------------------
// Softmax -> P fp16 (+ optional fp32 probs to out)
// ---------------------------------------------------------------------------
__global__ void __launch_bounds__(128) softmax_kernel(
    const float* __restrict__ scores, const int* __restrict__ dec, int masked,
    __half* __restrict__ P, float* __restrict__ outp)
{
    __shared__ float shm[32];
    const int row = blockIdx.x;
    const int q   = row & (SEQ - 1);
    const int bh  = row >> 9;
    const int b   = bh >> 4;
    const float* S = scores + (size_t)row * SEQ;
    const int* db = dec + b * SEQ;

    float v[4];
    float mx = -3.4e38f;
    #pragma unroll
    for (int u = 0; u < 4; ++u) {
        int k = threadIdx.x + u * 128;
        float s = S[k];
        if (masked && ((k > q) || (db[k] == 0))) s = -1e9f;
        v[u] = s;
        mx = fmaxf(mx, s);
    }
    mx = block_reduce_max(mx, shm);

    float sum = 0.f;
    #pragma unroll
    for (int u = 0; u < 4; ++u) {
        v[u] = expf(v[u] - mx);
        sum += v[u];
    }
    sum = block_reduce_sum(sum, shm);
    const float inv = 1.f / sum;

    #pragma unroll
    for (int u = 0; u < 4; ++u) {
        int k = threadIdx.x + u * 128;
        float p = v[u] * inv;
        P[(size_t)row * SEQ + k] = __float2half_rn(p);
        if (outp) outp[(size_t)row * SEQ + k] = p;
    }
}

// ---------------------------------------------------------------------------
// ctx (2-term): hi f32-accum, lo f16-accum. 3-stage pipeline + causal skip.
// ---------------------------------------------------------------------------
#define PPITCH 80
#define PTILE  (128 * PPITCH)          // 10240
#define VPITCH 144
#define VTILE  (32 * VPITCH)           // 4608
#define CTX_STG (PTILE + 2 * VTILE)    // 19456
#define CTX_NST 3
#define CTX_SMEM (CTX_NST * CTX_STG)   // 58368

__global__ void __launch_bounds__(256, 2)
attn_ctx_kernel(const __half* __restrict__ P,
                const __half* __restrict__ QKVh,
                const __half* __restrict__ QKVl,
                __half* __restrict__ C16, int masked)
{
    const int bh = blockIdx.y, b = bh >> 4, h = bh & 15;
    const int q0 = blockIdx.x * 128;

    extern __shared__ char smem[];
    const uint32_t sb = smem_u32(smem);
    const int tid = threadIdx.x;
    const int wid = tid >> 5, lane = tid & 31;
    const int wm = wid >> 2, wn = wid & 3;

    const __half* Pb = P + (size_t)bh * SEQ * SEQ;

    float acc[4][2][4];
    uint32_t accL[4][2][2];
    #pragma unroll
    for (int i = 0; i < 4; ++i)
        #pragma unroll
        for (int j = 0; j < 2; ++j) {
            #pragma unroll
            for (int t = 0; t < 4; ++t) acc[i][j][t] = 0.f;
            accL[i][j][0] = 0u; accL[i][j][1] = 0u;
        }

    auto load_stage = [&](int stage, int chunk) {
        const uint32_t st = sb + stage * CTX_STG;
        const int k0 = chunk * 32;
        {
            const int r  = tid >> 1;
            const int cb = (tid & 1) * 2;
            #pragma unroll
            for (int u = 0; u < 2; ++u) {
                const int c = cb + u;
                const uint32_t so = (uint32_t)(r * PPITCH + c * 16);
                cp16(st + so, Pb + (size_t)(q0 + r) * SEQ + k0 + c * 8);
            }
        }
        {
            const int r = tid >> 3, c = tid & 7;
            const uint32_t so = (uint32_t)(r * VPITCH + c * 16);
            const size_t gv = (size_t)(b * SEQ + k0 + r) * QKVN
                            + 2 * DMODEL + h * DHEAD + c * 8;
            cp16(st + PTILE + so,         QKVh + gv);
            cp16(st + PTILE + VTILE + so, QKVl + gv);
        }
    };

    const int NCHUNK = masked ? ((q0 >> 5) + 4) : (SEQ / 32);

    load_stage(0, 0); CP_COMMIT();
    if (NCHUNK > 1) load_stage(1, 1);
    CP_COMMIT();

    for (int ch = 0; ch < NCHUNK; ++ch) {
        CP_WAIT(1);
        __syncthreads();
        if (ch + 2 < NCHUNK) load_stage((ch + 2) % CTX_NST, ch + 2);
        CP_COMMIT();

        const uint32_t st = sb + (ch % CTX_NST) * CTX_STG;
        const uint32_t bP = st;
        const uint32_t bV = st + PTILE;

        #pragma unroll
        for (int ks = 0; ks < 2; ++ks) {
            const int kb = ks * 32;
            uint32_t fbh[2][2], fbl[2][2];
            #pragma unroll
            for (int nt = 0; nt < 2; ++nt) {
                uint32_t addr = bV
                    + (uint32_t)((ks * 16 + (lane & 15)) * VPITCH
                                 + (wn * 16 + nt * 8) * 2);
                ldsm_x2t(fbh[nt], addr);
                ldsm_x2t(fbl[nt], addr + VTILE);
            }
            #pragma unroll
            for (int mt = 0; mt < 4; ++mt) {
                uint32_t addr = bP
                    + (uint32_t)((wm * 64 + mt * 16 + (lane & 15)) * PPITCH
                                 + kb + (lane >> 4) * 16);
                uint32_t fa[4];
                ldsm_x4(fa, addr);
                #pragma unroll
                for (int nt = 0; nt < 2; ++nt) {
                    mma_f16(acc[mt][nt], fa, fbh[nt]);
                    mma_f16h(accL[mt][nt], fa, fbl[nt]);
                }
            }
        }
    }

    const int rbase = b * SEQ + q0 + wm * 64 + (lane >> 2);
    const int cbase = h * DHEAD + wn * 16 + (lane & 3) * 2;
    #pragma unroll
    for (int mt = 0; mt < 4; ++mt) {
        #pragma unroll
        for (int nt = 0; nt < 2; ++nt) {
            float* c = acc[mt][nt];
            comb(c, accL[mt][nt]);
            const int rr = rbase + mt * 16;
            const int cc = cbase + nt * 8;
            store_h2(C16, (size_t)rr * DMODEL + cc,       c[0], c[1]);
            store_h2(C16, (size_t)(rr + 8) * DMODEL + cc, c[2], c[3]);
        }
    }
}

// ---------------------------------------------------------------------------
// Weight transpose + split: W[l][K][N] fp32 -> out[l][N][K] fp16 hi/lo
// ---------------------------------------------------------------------------
__global__ void __launch_bounds__(256) convT_split_kernel(
    const float* __restrict__ W, __half* __restrict__ H,
    __half* __restrict__ L, int K, int N,
    size_t srcStride, size_t dstStride)
{
    __shared__ float t[32][33];
    const float* Wl = W + (size_t)blockIdx.z * srcStride;
    const size_t dofs = (size_t)blockIdx.z * dstStride;
    const int n0 = blockIdx.x * 32, k0 = blockIdx.y * 32;
    const int tx = threadIdx.x, ty = threadIdx.y;
    #pragma unroll
    for (int i = 0; i < 32; i += 8)
        t[ty + i][tx] = Wl[(size_t)(k0 + ty + i) * N + n0 + tx];
    __syncthreads();
    #pragma unroll
    for (int i = 0; i < 32; i += 8) {
        float v = t[tx][ty + i];
        __half h = __float2half_rn(v);
        __half l = __float2half_rn(v - __half2float(h));
        size_t o = dofs + (size_t)(n0 + ty + i) * K + k0 + tx;
        H[o] = h; L[o] = l;
    }
}

// ---------------------------------------------------------------------------
// Embedding (fp32 + fp16 hi/lo)
// ---------------------------------------------------------------------------
__global__ void embed_kernel(const int* __restrict__ dec,
                             const float* __restrict__ tok,
                             const float* __restrict__ pos,
                             float* __restrict__ x,
                             __half* __restrict__ xh,
                             __half* __restrict__ xl) {
    int row = blockIdx.x;
    int s   = row & (SEQ - 1);
    int t   = dec[row];
    const float* tp = tok + (size_t)t * DMODEL;
    const float* pp = pos + (size_t)s * DMODEL;
    size_t base = (size_t)row * DMODEL;
    #pragma unroll
    for (int u = 0; u < 4; ++u) {
        int c = threadIdx.x + u * 256;
        float v = tp[c] + pp[c];
        x[base + c] = v;
        __half h = __float2half_rn(v);
        xh[base + c] = h;
        xl[base + c] = __float2half_rn(v - __half2float(h));
    }
}

// ---------------------------------------------------------------------------
// out = LayerNorm(a + r) * g + beta  (fp32 + fp16 hi/lo)
// ---------------------------------------------------------------------------
__global__ void __launch_bounds__(256) add_ln_kernel(
    const float* __restrict__ a, const float* __restrict__ r,
    const float* __restrict__ g, const float* __restrict__ beta,
    float* __restrict__ out,
    __half* __restrict__ oh, __half* __restrict__ ol)
{
    __shared__ float shm[32];
    int row = blockIdx.x;
    const float* ap = a + (size_t)row * DMODEL;
    const float* rp = r + (size_t)row * DMODEL;
    size_t base = (size_t)row * DMODEL;

    float v[4];
    float s = 0.f;
    #pragma unroll
    for (int u = 0; u < 4; ++u) {
        int c = threadIdx.x + u * 256;
        v[u] = ap[c] + rp[c];
        s += v[u];
    }
    float mean = block_reduce_sum(s, shm) * (1.f / DMODEL);

    float sq = 0.f;
    #pragma unroll
    for (int u = 0; u < 4; ++u) {
        float d = v[u] - mean;
        sq += d * d;
    }
    float var = block_reduce_sum(sq, shm) * (1.f / DMODEL);
    float rstd = rsqrtf(var + 1e-5f);

    #pragma unroll
    for (int u = 0; u < 4; ++u) {
        int c = threadIdx.x + u * 256;
        float o = (v[u] - mean) * rstd * g[c] + beta[c];
        out[base + c] = o;
        __half h = __float2half_rn(o);
        oh[base + c] = h;
        ol[base + c] = __float2half_rn(o - __half2float(h));
    }
}

// ---------------------------------------------------------------------------
// Host orchestration
// ---------------------------------------------------------------------------
extern "C" void kernel_launch(void* const* d_in, const int* in_sizes, int n_in,
                              void* d_out, int out_size) {
    const int*   dec  = (const int*)  d_in[0];
    const float* tok  = (const float*)d_in[1];
    const float* pos  = (const float*)d_in[2];
    const float* Wq1  = (const float*)d_in[3];
    const float* Wk1  = (const float*)d_in[4];
    const float* Wv1  = (const float*)d_in[5];
    const float* Wo1  = (const float*)d_in[6];
    const float* g1   = (const float*)d_in[7];
    const float* b1   = (const float*)d_in[8];
    const float* Wq2  = (const float*)d_in[9];
    const float* Wk2  = (const float*)d_in[10];
    const float* Wv2  = (const float*)d_in[11];
    const float* Wo2  = (const float*)d_in[12];
    const float* g2   = (const float*)d_in[13];
    const float* b2   = (const float*)d_in[14];
    const float* Wff1 = (const float*)d_in[15];
    const float* Wff2 = (const float*)d_in[16];
    const float* gff  = (const float*)d_in[17];
    const float* bff  = (const float*)d_in[18];
    float* out = (float*)d_out;

    cudaFuncSetAttribute(mm_gemm3,
                         cudaFuncAttributeMaxDynamicSharedMemorySize, GEMM3_SMEM);
    cudaFuncSetAttribute(mm_gemm2,
                         cudaFuncAttributeMaxDynamicSharedMemorySize, GEMM2_SMEM);
    cudaFuncSetAttribute(attn_score_kernel,
                         cudaFuncAttributeMaxDynamicSharedMemorySize, SC_SMEM);
    cudaFuncSetAttribute(attn_ctx_kernel,
                         cudaFuncAttributeMaxDynamicSharedMemorySize, CTX_SMEM);

    float *x, *tmp, *sc;
    __half *xh, *xl, *qkvh, *qkvl, *c16, *f16, *p16, *wh, *wl;
    cudaGetSymbolAddress((void**)&x,    g_x);
    cudaGetSymbolAddress((void**)&tmp,  g_tmp);
    cudaGetSymbolAddress((void**)&sc,   g_sc);
    cudaGetSymbolAddress((void**)&xh,   g_xh);
    cudaGetSymbolAddress((void**)&xl,   g_xl);
    cudaGetSymbolAddress((void**)&qkvh, g_qkvh);
    cudaGetSymbolAddress((void**)&qkvl, g_qkvl);
    cudaGetSymbolAddress((void**)&c16,  g_c16);
    cudaGetSymbolAddress((void**)&f16,  g_f16);
    cudaGetSymbolAddress((void**)&p16,  g_p16);
    cudaGetSymbolAddress((void**)&wh,   g_wh);
    cudaGetSymbolAddress((void**)&wl,   g_wl);

    // ---- weight prep: transpose + split; QKV packed [3072,1024] ----
    dim3 tb(32, 8);
    dim3 gp(32, 32, LAYERS);
    convT_split_kernel<<<gp, tb>>>(Wq1, wh + OFF_QKV1 + 0 * MEG, wl + OFF_QKV1 + 0 * MEG, 1024, 1024, MEG, 3 * MEG);
    convT_split_kernel<<<gp, tb>>>(Wk1, wh + OFF_QKV1 + 1 * MEG, wl + OFF_QKV1 + 1 * MEG, 1024, 1024, MEG, 3 * MEG);
    convT_split_kernel<<<gp, tb>>>(Wv1, wh + OFF_QKV1 + 2 * MEG, wl + OFF_QKV1 + 2 * MEG, 1024, 1024, MEG, 3 * MEG);
    convT_split_kernel<<<gp, tb>>>(Wo1, wh + OFF_O1, wl + OFF_O1, 1024, 1024, MEG, MEG);
    convT_split_kernel<<<gp, tb>>>(Wq2, wh + OFF_QKV2 + 0 * MEG, wl + OFF_QKV2 + 0 * MEG, 1024, 1024, MEG, 3 * MEG);
    convT_split_kernel<<<gp, tb>>>(Wk2, wh + OFF_QKV2 + 1 * MEG, wl + OFF_QKV2 + 1 * MEG, 1024, 1024, MEG, 3 * MEG);
    convT_split_kernel<<<gp, tb>>>(Wv2, wh + OFF_QKV2 + 2 * MEG, wl + OFF_QKV2 + 2 * MEG, 1024, 1024, MEG, 3 * MEG);
    convT_split_kernel<<<gp, tb>>>(Wo2, wh + OFF_O2, wl + OFF_O2, 1024, 1024, MEG, MEG);
    convT_split_kernel<<<dim3(128, 32, LAYERS), tb>>>(Wff1, wh + OFF_F1, wl + OFF_F1, 1024, 4096, 4 * MEG, 4 * MEG);
    convT_split_kernel<<<dim3(32, 128, LAYERS), tb>>>(Wff2, wh + OFF_F2, wl + OFF_F2, 4096, 1024, 4 * MEG, 4 * MEG);

    const size_t ATTN_SZ = (size_t)BH * SEQ * SEQ;
    const size_t XN = (size_t)ROWS * DMODEL;

    embed_kernel<<<ROWS, 256>>>(dec, tok, pos, x, xh, xl);

    dim3 sc_grid(SEQ / 128, SEQ / 128, BH);
    dim3 ctx_grid(SEQ / 128, BH);

    for (int i = 0; i < LAYERS; ++i) {
        const size_t l1 = (size_t)i * MEG;
        const size_t l3 = (size_t)i * 3 * MEG;
        const size_t l4 = (size_t)i * 4 * MEG;

        // ---- MHA1 (masked) ----
        mm_gemm3<<<dim3(QKVN / 128, ROWS / 128), 256, GEMM3_SMEM>>>(
            xh, xl, wh + OFF_QKV1 + l3, wl + OFF_QKV1 + l3,
            qkvh, qkvl, ROWS, QKVN, DMODEL);
        attn_score_kernel<<<sc_grid, 256, SC_SMEM>>>(qkvh, qkvl, sc, 1);
        softmax_kernel<<<BH * SEQ, 128>>>(sc, dec, 1, p16, nullptr);
        attn_ctx_kernel<<<ctx_grid, 256, CTX_SMEM>>>(p16, qkvh, qkvl, c16, 1);
        mm_gemm2<<<dim3(DMODEL / 128, ROWS / 128), 256, GEMM2_SMEM>>>(
            c16, wh + OFF_O1 + l1, wl + OFF_O1 + l1,
            tmp, nullptr, ROWS, DMODEL, DMODEL, 0);
        add_ln_kernel<<<ROWS, 256>>>(tmp, x, g1 + i * DMODEL, b1 + i * DMODEL, x, xh, xl);

        // ---- MHA2 (unmasked; probs -> out) ----
        mm_gemm3<<<dim3(QKVN / 128, ROWS / 128), 256, GEMM3_SMEM>>>(
            xh, xl, wh + OFF_QKV2 + l3, wl + OFF_QKV2 + l3,
            qkvh, qkvl, ROWS, QKVN, DMODEL);
        attn_score_kernel<<<sc_grid, 256, SC_SMEM>>>(qkvh, qkvl, sc, 0);
        softmax_kernel<<<BH * SEQ, 128>>>(sc, dec, 0, p16,
                                          out + XN + (size_t)i * ATTN_SZ);
        attn_ctx_kernel<<<ctx_grid, 256, CTX_SMEM>>>(p16, qkvh, qkvl, c16, 0);
        mm_gemm2<<<dim3(DMODEL / 128, ROWS / 128), 256, GEMM2_SMEM>>>(
            c16, wh + OFF_O2 + l1, wl + OFF_O2 + l1,
            tmp, nullptr, ROWS, DMODEL, DMODEL, 0);
        add_ln_kernel<<<ROWS, 256>>>(tmp, x, g2 + i * DMODEL, b2 + i * DMODEL, x, xh, xl);

        // ---- FFN ----
        mm_gemm2<<<dim3(DFF / 128, ROWS / 128), 256, GEMM2_SMEM>>>(
            xh, wh + OFF_F1 + l4, wl + OFF_F1 + l4,
            nullptr, f16, ROWS, DFF, DMODEL, 1);
        mm_gemm2<<<dim3(DMODEL / 128, ROWS / 128), 256, GEMM2_SMEM>>>(
            f16, wh + OFF_F2 + l4, wl + OFF_F2 + l4,
            tmp, nullptr, ROWS, DMODEL, DFF, 0);
        add_ln_kernel<<<ROWS, 256>>>(tmp, x, gff + i * DMODEL, bff + i * DMODEL, x, xh, xl);
    }

    cudaMemcpyAsync(out, x, XN * sizeof(float), cudaMemcpyDeviceToDevice, 0);
}

// round 15
// speedup vs baseline: 1.0885x; 1.0885x over previous
#include <cuda_runtime.h>
#include <cuda_fp16.h>
#include <cstdint>
#include <cstddef>

// ---------------------------------------------------------------------------
// Problem dims (fixed)
// ---------------------------------------------------------------------------
#define LAYERS 6
#define BATCH  4
#define SEQ    512
#define DMODEL 1024
#define NHEAD  16
#define DHEAD  64
#define DFF    4096
#define ROWS   (BATCH * SEQ)           // 2048
#define BH     (BATCH * NHEAD)         // 64
#define QKVN   (3 * DMODEL)            // 3072

// ---------------------------------------------------------------------------
// Scratch (device globals; no allocation allowed)
// ---------------------------------------------------------------------------
__device__ float g_x  [ROWS * DMODEL];
__device__ float g_tmp[ROWS * DMODEL];
__device__ float g_sc [(size_t)BH * SEQ * SEQ];

__device__ __half g_xh  [ROWS * DMODEL];
__device__ __half g_xl  [ROWS * DMODEL];
__device__ __half g_qkvh[(size_t)ROWS * QKVN];   // Q|K hi + V single
__device__ __half g_qkvl[(size_t)ROWS * QKVN];   // Q|K lo (V region unused)
__device__ __half g_c16 [ROWS * DMODEL];
__device__ __half g_f16 [(size_t)ROWS * DFF];
__device__ __half g_p16 [(size_t)BH * SEQ * SEQ];

#define MEG (1024 * 1024)
#define W_TOTAL ((size_t)96 * MEG)
__device__ __half g_wh[W_TOTAL];
__device__ __half g_wl[W_TOTAL];

#define OFF_QKV1 ((size_t)0 * MEG)
#define OFF_O1   ((size_t)18 * MEG)
#define OFF_QKV2 ((size_t)24 * MEG)
#define OFF_O2   ((size_t)42 * MEG)
#define OFF_F1   ((size_t)48 * MEG)
#define OFF_F2   ((size_t)72 * MEG)

// ---------------------------------------------------------------------------
// PTX helpers
// ---------------------------------------------------------------------------
__device__ __forceinline__ uint32_t smem_u32(const void* p) {
    uint32_t a;
    asm("{ .reg .u64 t; cvta.to.shared.u64 t, %1; cvt.u32.u64 %0, t; }"
        : "=r"(a) : "l"(p));
    return a;
}
__device__ __forceinline__ void cp16(uint32_t dst, const void* src) {
    asm volatile("cp.async.cg.shared.global [%0], [%1], 16;"
                 :: "r"(dst), "l"(src) : "memory");
}
#define CP_COMMIT() asm volatile("cp.async.commit_group;" ::: "memory")
#define CP_WAIT(n)  asm volatile("cp.async.wait_group %0;" :: "n"(n) : "memory")

__device__ __forceinline__ void ldsm_x4(uint32_t a[4], uint32_t addr) {
    asm volatile("ldmatrix.sync.aligned.m8n8.x4.shared.b16 {%0,%1,%2,%3}, [%4];"
                 : "=r"(a[0]), "=r"(a[1]), "=r"(a[2]), "=r"(a[3]) : "r"(addr));
}
__device__ __forceinline__ void ldsm_x2(uint32_t a[2], uint32_t addr) {
    asm volatile("ldmatrix.sync.aligned.m8n8.x2.shared.b16 {%0,%1}, [%2];"
                 : "=r"(a[0]), "=r"(a[1]) : "r"(addr));
}
__device__ __forceinline__ void ldsm_x2t(uint32_t a[2], uint32_t addr) {
    asm volatile("ldmatrix.sync.aligned.m8n8.x2.trans.shared.b16 {%0,%1}, [%2];"
                 : "=r"(a[0]), "=r"(a[1]) : "r"(addr));
}
__device__ __forceinline__ void mma_f16(float c[4], const uint32_t a[4],
                                        const uint32_t b[2]) {
    asm volatile("mma.sync.aligned.m16n8k16.row.col.f32.f16.f16.f32 "
                 "{%0,%1,%2,%3}, {%4,%5,%6,%7}, {%8,%9}, {%0,%1,%2,%3};"
                 : "+f"(c[0]), "+f"(c[1]), "+f"(c[2]), "+f"(c[3])
                 : "r"(a[0]), "r"(a[1]), "r"(a[2]), "r"(a[3]),
                   "r"(b[0]), "r"(b[1]));
}
__device__ __forceinline__ void store_h2(__half* H, size_t off, float a, float b) {
    __half2 hv;
    hv.x = __float2half_rn(a); hv.y = __float2half_rn(b);
    *(__half2*)(H + off) = hv;
}
__device__ __forceinline__ void store_split2(__half* H, __half* L,
                                             size_t off, float a, float b) {
    __half ha = __float2half_rn(a), hb = __float2half_rn(b);
    __half la = __float2half_rn(a - __half2float(ha));
    __half lb = __float2half_rn(b - __half2float(hb));
    __half2 hv; hv.x = ha; hv.y = hb;
    __half2 lv; lv.x = la; lv.y = lb;
    *(__half2*)(H + off) = hv;
    *(__half2*)(L + off) = lv;
}

// ---------------------------------------------------------------------------
// Common tile constants
// ---------------------------------------------------------------------------
#define BKC      32
#define APITCH   80
#define TILE_B   (128 * APITCH)        // 10240

// ---------------------------------------------------------------------------
// 3-term GEMM (QK): C = (Ah+Al) @ (Bh+Bl)^T, f32 accum, hi/lo out, ldc stride.
// ---------------------------------------------------------------------------
#define STG3_B   (4 * TILE_B)          // 40960
#define GEMM3_SMEM (2 * STG3_B)        // 81920

__global__ void __launch_bounds__(256, 2)
mm_gemm3(const __half* __restrict__ Ah, const __half* __restrict__ Al,
         const __half* __restrict__ Bh, const __half* __restrict__ Bl,
         __half* __restrict__ Ch, __half* __restrict__ Cl,
         int M, int N, int K, int ldc)
{
    extern __shared__ char smem[];
    const uint32_t sb = smem_u32(smem);
    const int tid = threadIdx.x;
    const int wid = tid >> 5, lane = tid & 31;
    const int wm = wid >> 2, wn = wid & 3;
    const int m0 = blockIdx.y * 128, n0 = blockIdx.x * 128;

    const int r0 = tid >> 1;
    const int c0 = (tid & 1) * 2;

    float acc[4][4][4];
    #pragma unroll
    for (int i = 0; i < 4; ++i)
        #pragma unroll
        for (int j = 0; j < 4; ++j)
            #pragma unroll
            for (int t = 0; t < 4; ++t) acc[i][j][t] = 0.f;

    const int NCHUNK = K / BKC;

    auto load_stage = [&](int stage, int chunk) {
        const uint32_t st = sb + stage * STG3_B;
        const int k0 = chunk * BKC;
        #pragma unroll
        for (int u = 0; u < 2; ++u) {
            const int c = c0 + u;
            const uint32_t so = (uint32_t)(r0 * APITCH + c * 16);
            const size_t ga = (size_t)(m0 + r0) * K + k0 + c * 8;
            const size_t gb = (size_t)(n0 + r0) * K + k0 + c * 8;
            cp16(st + 0 * TILE_B + so, Ah + ga);
            cp16(st + 1 * TILE_B + so, Al + ga);
            cp16(st + 2 * TILE_B + so, Bh + gb);
            cp16(st + 3 * TILE_B + so, Bl + gb);
        }
    };

    load_stage(0, 0);
    CP_COMMIT();

    for (int ch = 0; ch < NCHUNK; ++ch) {
        CP_WAIT(0);
        __syncthreads();
        if (ch + 1 < NCHUNK) load_stage((ch + 1) & 1, ch + 1);
        CP_COMMIT();

        const uint32_t st  = sb + (ch & 1) * STG3_B;
        const uint32_t bAh = st, bBh = st + 2 * TILE_B;

        #pragma unroll
        for (int ks = 0; ks < 2; ++ks) {
            const int kb = ks * 32;
            uint32_t fbh[4][2], fbl[4][2];
            #pragma unroll
            for (int nt = 0; nt < 4; ++nt) {
                uint32_t addr = bBh
                    + (uint32_t)((wn * 32 + nt * 8 + (lane & 7)) * APITCH
                                 + kb + ((lane >> 3) & 1) * 16);
                ldsm_x2(fbh[nt], addr);
                ldsm_x2(fbl[nt], addr + TILE_B);
            }
            #pragma unroll
            for (int mt = 0; mt < 4; ++mt) {
                uint32_t addr = bAh
                    + (uint32_t)((wm * 64 + mt * 16 + (lane & 15)) * APITCH
                                 + kb + (lane >> 4) * 16);
                uint32_t fah[4], fal[4];
                ldsm_x4(fah, addr);
                ldsm_x4(fal, addr + TILE_B);
                #pragma unroll
                for (int nt = 0; nt < 4; ++nt) {
                    mma_f16(acc[mt][nt], fah, fbh[nt]);
                    mma_f16(acc[mt][nt], fah, fbl[nt]);
                    mma_f16(acc[mt][nt], fal, fbh[nt]);
                }
            }
        }
        __syncthreads();
    }

    const int rbase = m0 + wm * 64 + (lane >> 2);
    const int cbase = n0 + wn * 32 + (lane & 3) * 2;
    #pragma unroll
    for (int mt = 0; mt < 4; ++mt) {
        #pragma unroll
        for (int nt = 0; nt < 4; ++nt) {
            const float* c = acc[mt][nt];
            const int rr = rbase + mt * 16;
            const int cc = cbase + nt * 8;
            store_split2(Ch, Cl, (size_t)rr * ldc + cc,       c[0], c[1]);
            store_split2(Ch, Cl, (size_t)(rr + 8) * ldc + cc, c[2], c[3]);
        }
    }
}

// ---------------------------------------------------------------------------
// 2-term GEMM (V/O/F1/F2): C = A @ (Bh+Bl)^T, f32 accum, 3-stage pipeline.
// Epilogue: optional fp32 Cf, optional single-fp16 C16 (stride ldc), relu.
// ---------------------------------------------------------------------------
#define STG2_B   (3 * TILE_B)          // 30720
#define G2_NST   3
#define GEMM2_SMEM (G2_NST * STG2_B)   // 92160

__global__ void __launch_bounds__(256, 2)
mm_gemm2(const __half* __restrict__ A,
         const __half* __restrict__ Bh, const __half* __restrict__ Bl,
         float* __restrict__ Cf, __half* __restrict__ C16,
         int M, int N, int K, int relu, int ldc)
{
    extern __shared__ char smem[];
    const uint32_t sb = smem_u32(smem);
    const int tid = threadIdx.x;
    const int wid = tid >> 5, lane = tid & 31;
    const int wm = wid >> 2, wn = wid & 3;
    const int m0 = blockIdx.y * 128, n0 = blockIdx.x * 128;

    const int r0 = tid >> 1;
    const int c0 = (tid & 1) * 2;

    float acc[4][4][4];
    #pragma unroll
    for (int i = 0; i < 4; ++i)
        #pragma unroll
        for (int j = 0; j < 4; ++j)
            #pragma unroll
            for (int t = 0; t < 4; ++t) acc[i][j][t] = 0.f;

    const int NCHUNK = K / BKC;

    auto load_stage = [&](int stage, int chunk) {
        const uint32_t st = sb + stage * STG2_B;
        const int k0 = chunk * BKC;
        #pragma unroll
        for (int u = 0; u < 2; ++u) {
            const int c = c0 + u;
            const uint32_t so = (uint32_t)(r0 * APITCH + c * 16);
            const size_t ga = (size_t)(m0 + r0) * K + k0 + c * 8;
            const size_t gb = (size_t)(n0 + r0) * K + k0 + c * 8;
            cp16(st + 0 * TILE_B + so, A + ga);
            cp16(st + 1 * TILE_B + so, Bh + gb);
            cp16(st + 2 * TILE_B + so, Bl + gb);
        }
    };

    load_stage(0, 0); CP_COMMIT();
    if (NCHUNK > 1) load_stage(1, 1);
    CP_COMMIT();

    for (int ch = 0; ch < NCHUNK; ++ch) {
        CP_WAIT(1);
        __syncthreads();
        if (ch + 2 < NCHUNK) load_stage((ch + 2) % G2_NST, ch + 2);
        CP_COMMIT();

        const uint32_t st  = sb + (ch % G2_NST) * STG2_B;
        const uint32_t bA  = st, bBh = st + TILE_B;

        #pragma unroll
        for (int ks = 0; ks < 2; ++ks) {
            const int kb = ks * 32;
            uint32_t fbh[4][2], fbl[4][2];
            #pragma unroll
            for (int nt = 0; nt < 4; ++nt) {
                uint32_t addr = bBh
                    + (uint32_t)((wn * 32 + nt * 8 + (lane & 7)) * APITCH
                                 + kb + ((lane >> 3) & 1) * 16);
                ldsm_x2(fbh[nt], addr);
                ldsm_x2(fbl[nt], addr + TILE_B);
            }
            #pragma unroll
            for (int mt = 0; mt < 4; ++mt) {
                uint32_t addr = bA
                    + (uint32_t)((wm * 64 + mt * 16 + (lane & 15)) * APITCH
                                 + kb + (lane >> 4) * 16);
                uint32_t fa[4];
                ldsm_x4(fa, addr);
                #pragma unroll
                for (int nt = 0; nt < 4; ++nt) {
                    mma_f16(acc[mt][nt], fa, fbh[nt]);
                    mma_f16(acc[mt][nt], fa, fbl[nt]);
                }
            }
        }
    }

    const int rbase = m0 + wm * 64 + (lane >> 2);
    const int cbase = n0 + wn * 32 + (lane & 3) * 2;
    #pragma unroll
    for (int mt = 0; mt < 4; ++mt) {
        #pragma unroll
        for (int nt = 0; nt < 4; ++nt) {
            float* c = acc[mt][nt];
            if (relu) {
                c[0] = fmaxf(c[0], 0.f); c[1] = fmaxf(c[1], 0.f);
                c[2] = fmaxf(c[2], 0.f); c[3] = fmaxf(c[3], 0.f);
            }
            const int rr = rbase + mt * 16;
            const int cc = cbase + nt * 8;
            if (Cf) {
                *(float2*)(Cf + (size_t)rr * ldc + cc)       = make_float2(c[0], c[1]);
                *(float2*)(Cf + (size_t)(rr + 8) * ldc + cc) = make_float2(c[2], c[3]);
            }
            if (C16) {
                store_h2(C16, (size_t)rr * ldc + cc,       c[0], c[1]);
                store_h2(C16, (size_t)(rr + 8) * ldc + cc, c[2], c[3]);
            }
        }
    }
}

// ---------------------------------------------------------------------------
// Attention scores (3-term fp16, f32 accum)
// ---------------------------------------------------------------------------
#define SPITCH 144
#define STILE  (128 * SPITCH)          // 18432
#define SC_SMEM (4 * STILE)            // 73728

__global__ void __launch_bounds__(256)
attn_score_kernel(const __half* __restrict__ QKVh,
                  const __half* __restrict__ QKVl,
                  float* __restrict__ sc, int masked)
{
    const int bh = blockIdx.z, b = bh >> 4, h = bh & 15;
    const int q0 = blockIdx.y * 128, k0 = blockIdx.x * 128;
    if (masked && k0 >= q0 + 128) return;

    extern __shared__ char smem[];
    const uint32_t sb = smem_u32(smem);
    const int tid = threadIdx.x;
    const int wid = tid >> 5, lane = tid & 31;
    const int wm = wid >> 2, wn = wid & 3;

    {
        const int r  = tid >> 1;
        const int cb = (tid & 1) * 4;
        #pragma unroll
        for (int u = 0; u < 4; ++u) {
            const int c = cb + u;
            const uint32_t so = (uint32_t)(r * SPITCH + c * 16);
            const size_t gq = (size_t)(b * SEQ + q0 + r) * QKVN + h * DHEAD + c * 8;
            const size_t gk = (size_t)(b * SEQ + k0 + r) * QKVN + DMODEL + h * DHEAD + c * 8;
            cp16(sb + 0 * STILE + so, QKVh + gq);
            cp16(sb + 1 * STILE + so, QKVl + gq);
            cp16(sb + 2 * STILE + so, QKVh + gk);
            cp16(sb + 3 * STILE + so, QKVl + gk);
        }
    }
    CP_COMMIT();
    CP_WAIT(0);
    __syncthreads();

    float acc[4][4][4];
    #pragma unroll
    for (int i = 0; i < 4; ++i)
        #pragma unroll
        for (int j = 0; j < 4; ++j)
            #pragma unroll
            for (int t = 0; t < 4; ++t) acc[i][j][t] = 0.f;

    #pragma unroll
    for (int ks = 0; ks < 4; ++ks) {
        const int kb = ks * 32;
        uint32_t fbh[4][2], fbl[4][2];
        #pragma unroll
        for (int nt = 0; nt < 4; ++nt) {
            uint32_t addr = sb + 2 * STILE
                + (uint32_t)((wn * 32 + nt * 8 + (lane & 7)) * SPITCH
                             + kb + ((lane >> 3) & 1) * 16);
            ldsm_x2(fbh[nt], addr);
            ldsm_x2(fbl[nt], addr + STILE);
        }
        #pragma unroll
        for (int mt = 0; mt < 4; ++mt) {
            uint32_t addr = sb
                + (uint32_t)((wm * 64 + mt * 16 + (lane & 15)) * SPITCH
                             + kb + (lane >> 4) * 16);
            uint32_t fah[4], fal[4];
            ldsm_x4(fah, addr);
            ldsm_x4(fal, addr + STILE);
            #pragma unroll
            for (int nt = 0; nt < 4; ++nt) {
                mma_f16(acc[mt][nt], fah, fbh[nt]);
                mma_f16(acc[mt][nt], fah, fbl[nt]);
                mma_f16(acc[mt][nt], fal, fbh[nt]);
            }
        }
    }

    float* S = sc + (size_t)bh * SEQ * SEQ;
    const int rbase = q0 + wm * 64 + (lane >> 2);
    const int cbase = k0 + wn * 32 + (lane & 3) * 2;
    #pragma unroll
    for (int mt = 0; mt < 4; ++mt) {
        #pragma unroll
        for (int nt = 0; nt < 4; ++nt) {
            const float* c = acc[mt][nt];
            const int rr = rbase + mt * 16;
            const int cc = cbase + nt * 8;
            *(float2*)(S + (size_t)rr * SEQ + cc) =
                make_float2(c[0] * 0.125f, c[1] * 0.125f);
            *(float2*)(S + (size_t)(rr + 8) * SEQ + cc) =
                make_float2(c[2] * 0.125f, c[3] * 0.125f);
        }
    }
}

// ---------------------------------------------------------------------------
// Block reductions
// ---------------------------------------------------------------------------
__device__ __forceinline__ float block_reduce_sum(float v, float* shm) {
    __syncthreads();
    int lane = threadIdx.x & 31, w = threadIdx.x >> 5;
    #pragma unroll
    for (int o = 16; o; o >>= 1) v += __shfl_xor_sync(0xffffffff, v, o);
    if (lane == 0) shm[w] = v;
    __syncthreads();
    int nw = blockDim.x >> 5;
    float r = (threadIdx.x < nw) ? shm[threadIdx.x] : 0.f;
    if (w == 0) {
        #pragma unroll
        for (int o = 16; o; o >>= 1) r += __shfl_xor_sync(0xffffffff, r, o);
        if (lane == 0) shm[0] = r;
    }
    __syncthreads();
    return shm[0];
}
__device__ __forceinline__ float block_reduce_max(float v, float* shm) {
    __syncthreads();
    int lane = threadIdx.x & 31, w = threadIdx.x >> 5;
    #pragma unroll
    for (int o = 16; o; o >>= 1) v = fmaxf(v, __shfl_xor_sync(0xffffffff, v, o));
    if (lane == 0) shm[w] = v;
    __syncthreads();
    int nw = blockDim.x >> 5;
    float r = (threadIdx.x < nw) ? shm[threadIdx.x] : -3.4e38f;
    if (w == 0) {
        #pragma unroll
        for (int o = 16; o; o >>= 1) r = fmaxf(r, __shfl_xor_sync(0xffffffff, r, o));
        if (lane == 0) shm[0] = r;
    }
    __syncthreads();
    return shm[0];
}

// ---------------------------------------------------------------------------
// Softmax -> P fp16 (+ optional fp32 probs to out)
// ---------------------------------------------------------------------------
__global__ void __launch_bounds__(128) softmax_kernel(
    const float* __restrict__ scores, const int* __restrict__ dec, int masked,
    __half* __restrict__ P, float* __restrict__ outp)
{
    __shared__ float shm[32];
    const int row = blockIdx.x;
    const int q   = row & (SEQ - 1);
    const int bh  = row >> 9;
    const int b   = bh >> 4;
    const float* S = scores + (size_t)row * SEQ;
    const int* db = dec + b * SEQ;

    float v[4];
    float mx = -3.4e38f;
    #pragma unroll
    for (int u = 0; u < 4; ++u) {
        int k = threadIdx.x + u * 128;
        float s = S[k];
        if (masked && ((k > q) || (db[k] == 0))) s = -1e9f;
        v[u] = s;
        mx = fmaxf(mx, s);
    }
    mx = block_reduce_max(mx, shm);

    float sum = 0.f;
    #pragma unroll
    for (int u = 0; u < 4; ++u) {
        v[u] = expf(v[u] - mx);
        sum += v[u];
    }
    sum = block_reduce_sum(sum, shm);
    const float inv = 1.f / sum;

    #pragma unroll
    for (int u = 0; u < 4; ++u) {
        int k = threadIdx.x + u * 128;
        float p = v[u] * inv;
        P[(size_t)row * SEQ + k] = __float2half_rn(p);
        if (outp) outp[(size_t)row * SEQ + k] = p;
    }
}

// ---------------------------------------------------------------------------
// ctx (1-term): ctx = P (fp16) @ V (fp16); out single fp16.
// 3-stage pipeline + causal chunk skip.
// ---------------------------------------------------------------------------
#define PPITCH 80
#define PTILE  (128 * PPITCH)          // 10240
#define VPITCH 144
#define VTILE  (32 * VPITCH)           // 4608
#define CTX_STG (PTILE + VTILE)        // 14848
#define CTX_NST 3
#define CTX_SMEM (CTX_NST * CTX_STG)   // 44544

__global__ void __launch_bounds__(256, 2)
attn_ctx_kernel(const __half* __restrict__ P,
                const __half* __restrict__ QKVh,
                __half* __restrict__ C16, int masked)
{
    const int bh = blockIdx.y, b = bh >> 4, h = bh & 15;
    const int q0 = blockIdx.x * 128;

    extern __shared__ char smem[];
    const uint32_t sb = smem_u32(smem);
    const int tid = threadIdx.x;
    const int wid = tid >> 5, lane = tid & 31;
    const int wm = wid >> 2, wn = wid & 3;

    const __half* Pb = P + (size_t)bh * SEQ * SEQ;

    float acc[4][2][4];
    #pragma unroll
    for (int i = 0; i < 4; ++i)
        #pragma unroll
        for (int j = 0; j < 2; ++j)
            #pragma unroll
            for (int t = 0; t < 4; ++t) acc[i][j][t] = 0.f;

    auto load_stage = [&](int stage, int chunk) {
        const uint32_t st = sb + stage * CTX_STG;
        const int k0 = chunk * 32;
        {
            const int r  = tid >> 1;
            const int cb = (tid & 1) * 2;
            #pragma unroll
            for (int u = 0; u < 2; ++u) {
                const int c = cb + u;
                const uint32_t so = (uint32_t)(r * PPITCH + c * 16);
                cp16(st + so, Pb + (size_t)(q0 + r) * SEQ + k0 + c * 8);
            }
        }
        if (tid < 256) {
            const int r = tid >> 3, c = tid & 7;
            const uint32_t so = (uint32_t)(r * VPITCH + c * 16);
            const size_t gv = (size_t)(b * SEQ + k0 + r) * QKVN
                            + 2 * DMODEL + h * DHEAD + c * 8;
            cp16(st + PTILE + so, QKVh + gv);
        }
    };

    const int NCHUNK = masked ? ((q0 >> 5) + 4) : (SEQ / 32);

    load_stage(0, 0); CP_COMMIT();
    if (NCHUNK > 1) load_stage(1, 1);
    CP_COMMIT();

    for (int ch = 0; ch < NCHUNK; ++ch) {
        CP_WAIT(1);
        __syncthreads();
        if (ch + 2 < NCHUNK) load_stage((ch + 2) % CTX_NST, ch + 2);
        CP_COMMIT();

        const uint32_t st = sb + (ch % CTX_NST) * CTX_STG;
        const uint32_t bP = st;
        const uint32_t bV = st + PTILE;

        #pragma unroll
        for (int ks = 0; ks < 2; ++ks) {
            const int kb = ks * 32;
            uint32_t fbh[2][2];
            #pragma unroll
            for (int nt = 0; nt < 2; ++nt) {
                uint32_t addr = bV
                    + (uint32_t)((ks * 16 + (lane & 15)) * VPITCH
                                 + (wn * 16 + nt * 8) * 2);
                ldsm_x2t(fbh[nt], addr);
            }
            #pragma unroll
            for (int mt = 0; mt < 4; ++mt) {
                uint32_t addr = bP
                    + (uint32_t)((wm * 64 + mt * 16 + (lane & 15)) * PPITCH
                                 + kb + (lane >> 4) * 16);
                uint32_t fa[4];
                ldsm_x4(fa, addr);
                #pragma unroll
                for (int nt = 0; nt < 2; ++nt)
                    mma_f16(acc[mt][nt], fa, fbh[nt]);
            }
        }
    }

    const int rbase = b * SEQ + q0 + wm * 64 + (lane >> 2);
    const int cbase = h * DHEAD + wn * 16 + (lane & 3) * 2;
    #pragma unroll
    for (int mt = 0; mt < 4; ++mt) {
        #pragma unroll
        for (int nt = 0; nt < 2; ++nt) {
            const float* c = acc[mt][nt];
            const int rr = rbase + mt * 16;
            const int cc = cbase + nt * 8;
            store_h2(C16, (size_t)rr * DMODEL + cc,       c[0], c[1]);
            store_h2(C16, (size_t)(rr + 8) * DMODEL + cc, c[2], c[3]);
        }
    }
}

// ---------------------------------------------------------------------------
// Weight transpose + split: W[l][K][N] fp32 -> out[l][N][K] fp16 hi/lo
// ---------------------------------------------------------------------------
__global__ void __launch_bounds__(256) convT_split_kernel(
    const float* __restrict__ W, __half* __restrict__ H,
    __half* __restrict__ L, int K, int N,
    size_t srcStride, size_t dstStride)
{
    __shared__ float t[32][33];
    const float* Wl = W + (size_t)blockIdx.z * srcStride;
    const size_t dofs = (size_t)blockIdx.z * dstStride;
    const int n0 = blockIdx.x * 32, k0 = blockIdx.y * 32;
    const int tx = threadIdx.x, ty = threadIdx.y;
    #pragma unroll
    for (int i = 0; i < 32; i += 8)
        t[ty + i][tx] = Wl[(size_t)(k0 + ty + i) * N + n0 + tx];
    __syncthreads();
    #pragma unroll
    for (int i = 0; i < 32; i += 8) {
        float v = t[tx][ty + i];
        __half h = __float2half_rn(v);
        __half l = __float2half_rn(v - __half2float(h));
        size_t o = dofs + (size_t)(n0 + ty + i) * K + k0 + tx;
        H[o] = h; L[o] = l;
    }
}

// ---------------------------------------------------------------------------
// Embedding (fp32 + fp16 hi/lo)
// ---------------------------------------------------------------------------
__global__ void embed_kernel(const int* __restrict__ dec,
                             const float* __restrict__ tok,
                             const float* __restrict__ pos,
                             float* __restrict__ x,
                             __half* __restrict__ xh,
                             __half* __restrict__ xl) {
    int row = blockIdx.x;
    int s   = row & (SEQ - 1);
    int t   = dec[row];
    const float* tp = tok + (size_t)t * DMODEL;
    const float* pp = pos + (size_t)s * DMODEL;
    size_t base = (size_t)row * DMODEL;
    #pragma unroll
    for (int u = 0; u < 4; ++u) {
        int c = threadIdx.x + u * 256;
        float v = tp[c] + pp[c];
        x[base + c] = v;
        __half h = __float2half_rn(v);
        xh[base + c] = h;
        xl[base + c] = __float2half_rn(v - __half2float(h));
    }
}

// ---------------------------------------------------------------------------
// out = LayerNorm(a + r) * g + beta  (fp32 + fp16 hi/lo)
// ---------------------------------------------------------------------------
__global__ void __launch_bounds__(256) add_ln_kernel(
    const float* __restrict__ a, const float* __restrict__ r,
    const float* __restrict__ g, const float* __restrict__ beta,
    float* __restrict__ out,
    __half* __restrict__ oh, __half* __restrict__ ol)
{
    __shared__ float shm[32];
    int row = blockIdx.x;
    const float* ap = a + (size_t)row * DMODEL;
    const float* rp = r + (size_t)row * DMODEL;
    size_t base = (size_t)row * DMODEL;

    float v[4];
    float s = 0.f;
    #pragma unroll
    for (int u = 0; u < 4; ++u) {
        int c = threadIdx.x + u * 256;
        v[u] = ap[c] + rp[c];
        s += v[u];
    }
    float mean = block_reduce_sum(s, shm) * (1.f / DMODEL);

    float sq = 0.f;
    #pragma unroll
    for (int u = 0; u < 4; ++u) {
        float d = v[u] - mean;
        sq += d * d;
    }
    float var = block_reduce_sum(sq, shm) * (1.f / DMODEL);
    float rstd = rsqrtf(var + 1e-5f);

    #pragma unroll
    for (int u = 0; u < 4; ++u) {
        int c = threadIdx.x + u * 256;
        float o = (v[u] - mean) * rstd * g[c] + beta[c];
        out[base + c] = o;
        __half h = __float2half_rn(o);
        oh[base + c] = h;
        ol[base + c] = __float2half_rn(o - __half2float(h));
    }
}

// ---------------------------------------------------------------------------
// Host orchestration
// ---------------------------------------------------------------------------
extern "C" void kernel_launch(void* const* d_in, const int* in_sizes, int n_in,
                              void* d_out, int out_size) {
    const int*   dec  = (const int*)  d_in[0];
    const float* tok  = (const float*)d_in[1];
    const float* pos  = (const float*)d_in[2];
    const float* Wq1  = (const float*)d_in[3];
    const float* Wk1  = (const float*)d_in[4];
    const float* Wv1  = (const float*)d_in[5];
    const float* Wo1  = (const float*)d_in[6];
    const float* g1   = (const float*)d_in[7];
    const float* b1   = (const float*)d_in[8];
    const float* Wq2  = (const float*)d_in[9];
    const float* Wk2  = (const float*)d_in[10];
    const float* Wv2  = (const float*)d_in[11];
    const float* Wo2  = (const float*)d_in[12];
    const float* g2   = (const float*)d_in[13];
    const float* b2   = (const float*)d_in[14];
    const float* Wff1 = (const float*)d_in[15];
    const float* Wff2 = (const float*)d_in[16];
    const float* gff  = (const float*)d_in[17];
    const float* bff  = (const float*)d_in[18];
    float* out = (float*)d_out;

    cudaFuncSetAttribute(mm_gemm3,
                         cudaFuncAttributeMaxDynamicSharedMemorySize, GEMM3_SMEM);
    cudaFuncSetAttribute(mm_gemm2,
                         cudaFuncAttributeMaxDynamicSharedMemorySize, GEMM2_SMEM);
    cudaFuncSetAttribute(attn_score_kernel,
                         cudaFuncAttributeMaxDynamicSharedMemorySize, SC_SMEM);
    cudaFuncSetAttribute(attn_ctx_kernel,
                         cudaFuncAttributeMaxDynamicSharedMemorySize, CTX_SMEM);

    float *x, *tmp, *sc;
    __half *xh, *xl, *qkvh, *qkvl, *c16, *f16, *p16, *wh, *wl;
    cudaGetSymbolAddress((void**)&x,    g_x);
    cudaGetSymbolAddress((void**)&tmp,  g_tmp);
    cudaGetSymbolAddress((void**)&sc,   g_sc);
    cudaGetSymbolAddress((void**)&xh,   g_xh);
    cudaGetSymbolAddress((void**)&xl,   g_xl);
    cudaGetSymbolAddress((void**)&qkvh, g_qkvh);
    cudaGetSymbolAddress((void**)&qkvl, g_qkvl);
    cudaGetSymbolAddress((void**)&c16,  g_c16);
    cudaGetSymbolAddress((void**)&f16,  g_f16);
    cudaGetSymbolAddress((void**)&p16,  g_p16);
    cudaGetSymbolAddress((void**)&wh,   g_wh);
    cudaGetSymbolAddress((void**)&wl,   g_wl);

    // ---- weight prep: transpose + split; QKV packed [3072,1024] ----
    dim3 tb(32, 8);
    dim3 gp(32, 32, LAYERS);
    convT_split_kernel<<<gp, tb>>>(Wq1, wh + OFF_QKV1 + 0 * MEG, wl + OFF_QKV1 + 0 * MEG, 1024, 1024, MEG, 3 * MEG);
    convT_split_kernel<<<gp, tb>>>(Wk1, wh + OFF_QKV1 + 1 * MEG, wl + OFF_QKV1 + 1 * MEG, 1024, 1024, MEG, 3 * MEG);
    convT_split_kernel<<<gp, tb>>>(Wv1, wh + OFF_QKV1 + 2 * MEG, wl + OFF_QKV1 + 2 * MEG, 1024, 1024, MEG, 3 * MEG);
    convT_split_kernel<<<gp, tb>>>(Wo1, wh + OFF_O1, wl + OFF_O1, 1024, 1024, MEG, MEG);
    convT_split_kernel<<<gp, tb>>>(Wq2, wh + OFF_QKV2 + 0 * MEG, wl + OFF_QKV2 + 0 * MEG, 1024, 1024, MEG, 3 * MEG);
    convT_split_kernel<<<gp, tb>>>(Wk2, wh + OFF_QKV2 + 1 * MEG, wl + OFF_QKV2 + 1 * MEG, 1024, 1024, MEG, 3 * MEG);
    convT_split_kernel<<<gp, tb>>>(Wv2, wh + OFF_QKV2 + 2 * MEG, wl + OFF_QKV2 + 2 * MEG, 1024, 1024, MEG, 3 * MEG);
    convT_split_kernel<<<gp, tb>>>(Wo2, wh + OFF_O2, wl + OFF_O2, 1024, 1024, MEG, MEG);
    convT_split_kernel<<<dim3(128, 32, LAYERS), tb>>>(Wff1, wh + OFF_F1, wl + OFF_F1, 1024, 4096, 4 * MEG, 4 * MEG);
    convT_split_kernel<<<dim3(32, 128, LAYERS), tb>>>(Wff2, wh + OFF_F2, wl + OFF_F2, 4096, 1024, 4 * MEG, 4 * MEG);

    const size_t ATTN_SZ = (size_t)BH * SEQ * SEQ;
    const size_t XN = (size_t)ROWS * DMODEL;

    embed_kernel<<<ROWS, 256>>>(dec, tok, pos, x, xh, xl);

    dim3 sc_grid(SEQ / 128, SEQ / 128, BH);
    dim3 ctx_grid(SEQ / 128, BH);

    for (int i = 0; i < LAYERS; ++i) {
        const size_t l1 = (size_t)i * MEG;
        const size_t l3 = (size_t)i * 3 * MEG;
        const size_t l4 = (size_t)i * 4 * MEG;

        // ---- MHA1 (masked) ----
        // QK: 3-term (N=2048); V: 2-term single-fp16 out (N=1024)
        mm_gemm3<<<dim3(2048 / 128, ROWS / 128), 256, GEMM3_SMEM>>>(
            xh, xl, wh + OFF_QKV1 + l3, wl + OFF_QKV1 + l3,
            qkvh, qkvl, ROWS, 2048, DMODEL, QKVN);
        mm_gemm2<<<dim3(DMODEL / 128, ROWS / 128), 256, GEMM2_SMEM>>>(
            xh, wh + OFF_QKV1 + l3 + 2 * MEG, wl + OFF_QKV1 + l3 + 2 * MEG,
            nullptr, qkvh + 2 * DMODEL, ROWS, DMODEL, DMODEL, 0, QKVN);
        attn_score_kernel<<<sc_grid, 256, SC_SMEM>>>(qkvh, qkvl, sc, 1);
        softmax_kernel<<<BH * SEQ, 128>>>(sc, dec, 1, p16, nullptr);
        attn_ctx_kernel<<<ctx_grid, 256, CTX_SMEM>>>(p16, qkvh, c16, 1);
        mm_gemm2<<<dim3(DMODEL / 128, ROWS / 128), 256, GEMM2_SMEM>>>(
            c16, wh + OFF_O1 + l1, wl + OFF_O1 + l1,
            tmp, nullptr, ROWS, DMODEL, DMODEL, 0, DMODEL);
        add_ln_kernel<<<ROWS, 256>>>(tmp, x, g1 + i * DMODEL, b1 + i * DMODEL, x, xh, xl);

        // ---- MHA2 (unmasked; probs -> out) ----
        mm_gemm3<<<dim3(2048 / 128, ROWS / 128), 256, GEMM3_SMEM>>>(
            xh, xl, wh + OFF_QKV2 + l3, wl + OFF_QKV2 + l3,
            qkvh, qkvl, ROWS, 2048, DMODEL, QKVN);
        mm_gemm2<<<dim3(DMODEL / 128, ROWS / 128), 256, GEMM2_SMEM>>>(
            xh, wh + OFF_QKV2 + l3 + 2 * MEG, wl + OFF_QKV2 + l3 + 2 * MEG,
            nullptr, qkvh + 2 * DMODEL, ROWS, DMODEL, DMODEL, 0, QKVN);
        attn_score_kernel<<<sc_grid, 256, SC_SMEM>>>(qkvh, qkvl, sc, 0);
        softmax_kernel<<<BH * SEQ, 128>>>(sc, dec, 0, p16,
                                          out + XN + (size_t)i * ATTN_SZ);
        attn_ctx_kernel<<<ctx_grid, 256, CTX_SMEM>>>(p16, qkvh, c16, 0);
        mm_gemm2<<<dim3(DMODEL / 128, ROWS / 128), 256, GEMM2_SMEM>>>(
            c16, wh + OFF_O2 + l1, wl + OFF_O2 + l1,
            tmp, nullptr, ROWS, DMODEL, DMODEL, 0, DMODEL);
        add_ln_kernel<<<ROWS, 256>>>(tmp, x, g2 + i * DMODEL, b2 + i * DMODEL, x, xh, xl);

        // ---- FFN ----
        mm_gemm2<<<dim3(DFF / 128, ROWS / 128), 256, GEMM2_SMEM>>>(
            xh, wh + OFF_F1 + l4, wl + OFF_F1 + l4,
            nullptr, f16, ROWS, DFF, DMODEL, 1, DFF);
        mm_gemm2<<<dim3(DMODEL / 128, ROWS / 128), 256, GEMM2_SMEM>>>(
            f16, wh + OFF_F2 + l4, wl + OFF_F2 + l4,
            tmp, nullptr, ROWS, DMODEL, DFF, 0, DMODEL);
        add_ln_kernel<<<ROWS, 256>>>(tmp, x, gff + i * DMODEL, bff + i * DMODEL, x, xh, xl);
    }

    cudaMemcpyAsync(out, x, XN * sizeof(float), cudaMemcpyDeviceToDevice, 0);
}